// round 12
// baseline (speedup 1.0000x reference)
#include <cuda_runtime.h>
#include <cuda_fp16.h>
#include <cstdint>

// Problem constants (fixed by the reference)
#define NMAX 100000
#define EMAX 1250000
#define HDIM 64
#define NCLS 10
#define SCAN_CHUNK 1024
#define MAXBLK 128   // ceil(NMAX/SCAN_CHUNK) = 98 <= 128

typedef unsigned long long ull;

// Packed fp32x2 helpers (Blackwell PTX; rounding identical to fmaf)
#define FMA2(d, a, b, c) \
    asm("fma.rn.f32x2 %0, %1, %2, %3;" : "=l"(d) : "l"(a), "l"(b), "l"(c))
#define PACK2(out, lo, hi) \
    asm("mov.b64 %0, {%1, %2};" : "=l"(out) : "f"(lo), "f"(hi))
#define UNPACK2(lo, hi, in) \
    asm("mov.b64 {%0, %1}, %2;" : "=f"(lo), "=f"(hi) : "l"(in))

// Scratch: __device__ globals (allocation APIs are forbidden).
__device__ __align__(16)  float  g_t2[NMAX * HDIM];   // fp32 messages (self term)
__device__ __align__(128) __half g_t2h[NMAX * HDIM];  // fp16 messages (neighbor reads)
__device__ __align__(16)  float  g_h [NMAX * HDIM];   // layer output
__device__ float g_dinv[NMAX];
__device__ int   g_cnt[NMAX];
__device__ int   g_rowptr[NMAX + 1];
__device__ int   g_eidx[EMAX];
__device__ int   g_bsum[MAXBLK];
__device__ int   g_boff[MAXBLK];

// ---------------------------------------------------------------------------
__global__ void k_zerocnt(int n) {
    int i = blockIdx.x * blockDim.x + threadIdx.x;
    if (i < n) g_cnt[i] = 0;
}

__global__ void k_hist(const int* __restrict__ ei, int e, int n) {
    int idx = blockIdx.x * blockDim.x + threadIdx.x;
    if (idx < e) {
        int d = ei[e + idx];
        if (d >= 0 && d < n) atomicAdd(&g_cnt[d], 1);
    }
}

__global__ void k_dinvk(int n) {
    int i = blockIdx.x * blockDim.x + threadIdx.x;
    if (i < n) g_dinv[i] = rsqrtf((float)(g_cnt[i] + 1));
}

// ---------------------------------------------------------------------------
// Parallel 3-phase exclusive scan of g_cnt -> g_rowptr.
__global__ void k_blocksum(int n) {
    const int t = threadIdx.x;
    const int base = blockIdx.x * SCAN_CHUNK + t * 4;
    int s = 0;
#pragma unroll
    for (int j = 0; j < 4; j++) {
        int i = base + j;
        if (i < n) s += g_cnt[i];
    }
#pragma unroll
    for (int off = 16; off > 0; off >>= 1)
        s += __shfl_down_sync(0xffffffffu, s, off);
    __shared__ int wsum[8];
    if ((t & 31) == 0) wsum[t >> 5] = s;
    __syncthreads();
    if (t == 0) {
        int tot = 0;
#pragma unroll
        for (int w = 0; w < 8; w++) tot += wsum[w];
        g_bsum[blockIdx.x] = tot;
    }
}

__global__ void k_scanb(int nb, int n) {
    const int t = threadIdx.x;       // 128 threads
    int v = (t < nb) ? g_bsum[t] : 0;
    int own = v;
    int lane = t & 31, w = t >> 5;
#pragma unroll
    for (int off = 1; off < 32; off <<= 1) {
        int u = __shfl_up_sync(0xffffffffu, v, off);
        if (lane >= off) v += u;
    }
    __shared__ int wtot[4], woff[4];
    if (lane == 31) wtot[w] = v;
    __syncthreads();
    if (t == 0) {
        int run = 0;
#pragma unroll
        for (int i = 0; i < 4; i++) { woff[i] = run; run += wtot[i]; }
        g_rowptr[n] = run;           // total edge count
    }
    __syncthreads();
    int incl = v + woff[w];
    if (t < nb) g_boff[t] = incl - own;   // exclusive
}

__global__ void k_rowptr(int n) {
    const int t = threadIdx.x;       // 256 threads
    const int base = blockIdx.x * SCAN_CHUNK + t * 4;
    int c[4];
    int s = 0;
#pragma unroll
    for (int j = 0; j < 4; j++) {
        int i = base + j;
        c[j] = (i < n) ? g_cnt[i] : 0;
        s += c[j];
    }
    int v = s, own = s;
    int lane = t & 31, w = t >> 5;
#pragma unroll
    for (int off = 1; off < 32; off <<= 1) {
        int u = __shfl_up_sync(0xffffffffu, v, off);
        if (lane >= off) v += u;
    }
    __shared__ int wtot[8], woff[8];
    if (lane == 31) wtot[w] = v;
    __syncthreads();
    if (t == 0) {
        int run = 0;
#pragma unroll
        for (int i = 0; i < 8; i++) { woff[i] = run; run += wtot[i]; }
    }
    __syncthreads();
    int excl = (v - own) + woff[w] + g_boff[blockIdx.x];
#pragma unroll
    for (int j = 0; j < 4; j++) {
        int i = base + j;
        if (i < n) {
            g_rowptr[i] = excl;
            excl += c[j];
            g_cnt[i] = 0;            // reset fill cursor
        }
    }
}

__global__ void k_fill(const int* __restrict__ ei, int e, int n) {
    int idx = blockIdx.x * blockDim.x + threadIdx.x;
    if (idx < e) {
        int s = ei[idx];
        int d = ei[e + idx];
        if (s >= 0 && s < n && d >= 0 && d < n) {
            int pos = g_rowptr[d] + atomicAdd(&g_cnt[d], 1);
            if (pos < EMAX) g_eidx[pos] = s;
        }
    }
}

// ---------------------------------------------------------------------------
// Register-tiled GEMM: t2 = dinv ⊙ ((relu?)hin @ W), fp32 + fp16 outputs.
// BM=128 rows/block, 256 threads: ty=tid>>3 (32), tx=tid&7 (8).
// Thread computes rows {ty+32*i, i=0..3} x cols [tx*8, tx*8+8).
// 4 blocks/SM (48KB smem, ~64 regs) -> 32 warps resident (2x round-11 occ).
// Hsh XOR-swizzled so the per-row scalar loads are bank-conflict-free
// (rows ty+32i share ty&3, so one kswz per thread).
// Accumulation via packed fma.rn.f32x2 (2 fp32 FMA per instruction).
__global__ void __launch_bounds__(256) k_matmul(
        const float* __restrict__ xin, int use_x,
        const float* __restrict__ W, int n, int relu) {
    __shared__ float Hsh[128 * 64];  // [row][k ^ ((row&3)<<3)]
    __shared__ float Wsh[64 * 64];   // [k][col]

    const float* hin = use_x ? xin : g_h;
    const int tid = threadIdx.x;
    const int r0  = blockIdx.x * 128;

    // Load W (64x64) coalesced: 1024 float4 / 256 threads = 4 iters
    {
        const float4* W4 = (const float4*)W;
        float4* Wsh4 = (float4*)Wsh;
#pragma unroll
        for (int i = 0; i < 4; i++) Wsh4[tid + 256 * i] = W4[tid + 256 * i];
    }

    // Load H tile (128 rows x 64 cols) with XOR swizzle, optional relu.
#pragma unroll
    for (int i = 0; i < 8; i++) {
        int idx = tid + 256 * i;        // 0..2047 float4 slots
        int row = idx >> 4;
        int c4  = idx & 15;
        int gr  = r0 + row;
        float4 v = make_float4(0.f, 0.f, 0.f, 0.f);
        if (gr < n) v = *(const float4*)(hin + (size_t)gr * 64 + c4 * 4);
        if (relu) {
            v.x = fmaxf(v.x, 0.f); v.y = fmaxf(v.y, 0.f);
            v.z = fmaxf(v.z, 0.f); v.w = fmaxf(v.w, 0.f);
        }
        int col = (c4 * 4) ^ ((row & 3) << 3);   // swizzled column base
        *(float4*)&Hsh[row * 64 + col] = v;
    }
    __syncthreads();

    const int ty = tid >> 3;         // 0..31
    const int tx = tid & 7;          // 0..7
    const int kswz = (ty & 3) << 3;  // per-thread constant XOR

    ull acc[4][4];
#pragma unroll
    for (int i = 0; i < 4; i++)
#pragma unroll
        for (int j = 0; j < 4; j++) acc[i][j] = 0ull;

#pragma unroll 8
    for (int k = 0; k < 64; k++) {
        const int kx = k ^ kswz;
        ull ad[4];
#pragma unroll
        for (int i = 0; i < 4; i++) {
            float a = Hsh[(ty + 32 * i) * 64 + kx];
            PACK2(ad[i], a, a);
        }
        const ull* Wp = (const ull*)(Wsh + k * 64 + tx * 8);
        ull b0 = Wp[0], b1 = Wp[1], b2 = Wp[2], b3 = Wp[3];
#pragma unroll
        for (int i = 0; i < 4; i++) {
            FMA2(acc[i][0], ad[i], b0, acc[i][0]);
            FMA2(acc[i][1], ad[i], b1, acc[i][1]);
            FMA2(acc[i][2], ad[i], b2, acc[i][2]);
            FMA2(acc[i][3], ad[i], b3, acc[i][3]);
        }
    }

    // Epilogue: scale by dinv, write fp32 t2 + fp16 t2h
#pragma unroll
    for (int i = 0; i < 4; i++) {
        int row = r0 + ty + 32 * i;
        if (row >= n) continue;
        float di = g_dinv[row];
        float o[8];
#pragma unroll
        for (int j = 0; j < 4; j++) {
            float lo, hi;
            UNPACK2(lo, hi, acc[i][j]);
            o[2 * j]     = lo * di;
            o[2 * j + 1] = hi * di;
        }
        size_t base = (size_t)row * 64 + tx * 8;
        *(float4*)(g_t2 + base)     = make_float4(o[0], o[1], o[2], o[3]);
        *(float4*)(g_t2 + base + 4) = make_float4(o[4], o[5], o[6], o[7]);
        __half2 h0 = __floats2half2_rn(o[0], o[1]);
        __half2 h1 = __floats2half2_rn(o[2], o[3]);
        __half2 h2 = __floats2half2_rn(o[4], o[5]);
        __half2 h3 = __floats2half2_rn(o[6], o[7]);
        uint4 hp;
        hp.x = *(const unsigned int*)&h0;
        hp.y = *(const unsigned int*)&h1;
        hp.z = *(const unsigned int*)&h2;
        hp.w = *(const unsigned int*)&h3;
        *(uint4*)(g_t2h + base) = hp;
    }
}

// ---------------------------------------------------------------------------
// Gather: h[i] = dinv[i]*(t2[i] + sum_{e: dst=i} fp16(t2[src_e])) + b
// 16 threads per node; neighbor rows read as fp16 (8 B/thread), fp32 accum.
__global__ void k_gather(const float* __restrict__ b, int n) {
    int gid = blockIdx.x * blockDim.x + threadIdx.x;
    int node = gid >> 4;
    if (node >= n) return;
    int q = (gid & 15) << 2;

    float4 acc = *(const float4*)(g_t2 + ((size_t)node << 6) + q);
    float4 acc2 = make_float4(0.f, 0.f, 0.f, 0.f);

    int k   = g_rowptr[node];
    int end = g_rowptr[node + 1];

    const __half* t2h = g_t2h;

    for (; k + 4 <= end; k += 4) {
        int s0 = __ldg(&g_eidx[k]);
        int s1 = __ldg(&g_eidx[k + 1]);
        int s2 = __ldg(&g_eidx[k + 2]);
        int s3 = __ldg(&g_eidx[k + 3]);
        uint2 r0 = *(const uint2*)(t2h + ((size_t)s0 << 6) + q);
        uint2 r1 = *(const uint2*)(t2h + ((size_t)s1 << 6) + q);
        uint2 r2 = *(const uint2*)(t2h + ((size_t)s2 << 6) + q);
        uint2 r3 = *(const uint2*)(t2h + ((size_t)s3 << 6) + q);
        float2 a0 = __half22float2(*(const __half2*)&r0.x);
        float2 b0 = __half22float2(*(const __half2*)&r0.y);
        float2 a1 = __half22float2(*(const __half2*)&r1.x);
        float2 b1 = __half22float2(*(const __half2*)&r1.y);
        float2 a2 = __half22float2(*(const __half2*)&r2.x);
        float2 b2 = __half22float2(*(const __half2*)&r2.y);
        float2 a3 = __half22float2(*(const __half2*)&r3.x);
        float2 b3 = __half22float2(*(const __half2*)&r3.y);
        acc.x  += a0.x + a1.x;  acc.y  += a0.y + a1.y;
        acc.z  += b0.x + b1.x;  acc.w  += b0.y + b1.y;
        acc2.x += a2.x + a3.x;  acc2.y += a2.y + a3.y;
        acc2.z += b2.x + b3.x;  acc2.w += b2.y + b3.y;
    }
    for (; k < end; k++) {
        int s0 = __ldg(&g_eidx[k]);
        uint2 r0 = *(const uint2*)(t2h + ((size_t)s0 << 6) + q);
        float2 a0 = __half22float2(*(const __half2*)&r0.x);
        float2 b0 = __half22float2(*(const __half2*)&r0.y);
        acc.x += a0.x; acc.y += a0.y; acc.z += b0.x; acc.w += b0.y;
    }
    acc.x += acc2.x; acc.y += acc2.y; acc.z += acc2.z; acc.w += acc2.w;

    float di = g_dinv[node];
    float4 bb = *(const float4*)(b + q);
    float4 o;
    o.x = fmaf(di, acc.x, bb.x);
    o.y = fmaf(di, acc.y, bb.y);
    o.z = fmaf(di, acc.z, bb.z);
    o.w = fmaf(di, acc.w, bb.w);
    *(float4*)(g_h + ((size_t)node << 6) + q) = o;
}

// ---------------------------------------------------------------------------
// Fused mean-pool (batch sorted -> binary search segments) + linear head.
__global__ void k_pool(const int* __restrict__ batch,
                       const float* __restrict__ Wl, const float* __restrict__ bl,
                       float* __restrict__ out, int n) {
    const float* h = g_h;
    const int g = blockIdx.x;
    const int t = threadIdx.x;
    const int c = t & 63;
    const int j = t >> 6;

    auto lb = [&](int key) {
        int lo = 0, hi = n;
        while (lo < hi) {
            int mid = (lo + hi) >> 1;
            if (batch[mid] < key) lo = mid + 1; else hi = mid;
        }
        return lo;
    };
    int lo = lb(g);
    int hi = lb(g + 1);
    int cnt = hi - lo;

    float s = 0.f;
    for (int i = lo + j; i < hi; i += 4)
        s += h[(size_t)i * 64 + c];

    __shared__ float red[256];
    red[t] = s;
    __syncthreads();

    __shared__ float pooled[64];
    if (t < 64) {
        float tot = red[t] + red[t + 64] + red[t + 128] + red[t + 192];
        pooled[t] = tot / (float)max(cnt, 1);
    }
    __syncthreads();

    if (t < NCLS) {
        float acc = bl[t];
#pragma unroll
        for (int k = 0; k < 64; k++)
            acc = fmaf(pooled[k], Wl[k * NCLS + t], acc);
        out[g * NCLS + t] = acc;
    }
}

// ---------------------------------------------------------------------------
extern "C" void kernel_launch(void* const* d_in, const int* in_sizes, int n_in,
                              void* d_out, int out_size) {
    // Resolve inputs BY ELEMENT COUNT (robust to metadata ordering).
    const float* x     = nullptr;
    const int*   ei    = nullptr;
    const int*   batch = nullptr;
    const float* W[3] = {nullptr, nullptr, nullptr};
    const float* B[3] = {nullptr, nullptr, nullptr};
    const float* Wl = nullptr;
    const float* bl = nullptr;
    int nW = 0, nB = 0;
    long long eiCount = 0, batchCount = 0;

    for (int i = 0; i < n_in; i++) {
        long long sz = in_sizes[i];
        if (sz == 10)            bl = (const float*)d_in[i];
        else if (sz == 640)      Wl = (const float*)d_in[i];
        else if (sz == HDIM)     { if (nB < 3) B[nB++] = (const float*)d_in[i]; }
        else if (sz == HDIM*HDIM){ if (nW < 3) W[nW++] = (const float*)d_in[i]; }
        else {
            if (sz >= 6000000)       x = (const float*)d_in[i];
            else if (sz >= 2000000)  { ei = (const int*)d_in[i]; eiCount = sz; }
            else                     { batch = (const int*)d_in[i]; batchCount = sz; }
        }
    }

    float* out = (float*)d_out;
    const int n = (int)batchCount;            // N nodes
    const int e = (int)(eiCount / 2);         // E edges
    const int g = out_size / NCLS;            // G graphs

    const int tb = 256;
    const int nb = (n + SCAN_CHUNK - 1) / SCAN_CHUNK;   // scan blocks (98)
    const int mmGrid = (n + 127) / 128;
    const int gaGrid = (n * 16 + tb - 1) / tb;

    // Launch order keeps matmul layer-1 at slot #4 (the ncu-captured launch).
    k_zerocnt <<<(n + tb - 1) / tb, tb>>>(n);            // 1
    k_hist    <<<(e + tb - 1) / tb, tb>>>(ei, e, n);     // 2
    k_dinvk   <<<(n + tb - 1) / tb, tb>>>(n);            // 3
    k_matmul  <<<mmGrid, 256>>>(x, 1, W[0], n, 0);       // 4  <- profiled
    k_blocksum<<<nb, tb>>>(n);                           // 5
    k_scanb   <<<1, 128>>>(nb, n);                       // 6
    k_rowptr  <<<nb, tb>>>(n);                           // 7
    k_fill    <<<(e + tb - 1) / tb, tb>>>(ei, e, n);     // 8
    k_gather  <<<gaGrid, tb>>>(B[0], n);                 // 9
    k_matmul  <<<mmGrid, 256>>>(nullptr, 0, W[1], n, 1); // 10
    k_gather  <<<gaGrid, tb>>>(B[1], n);                 // 11
    k_matmul  <<<mmGrid, 256>>>(nullptr, 0, W[2], n, 1); // 12
    k_gather  <<<gaGrid, tb>>>(B[2], n);                 // 13
    k_pool    <<<g, tb>>>(batch, Wl, bl, out, n);        // 14
}

// round 13
// speedup vs baseline: 1.5477x; 1.5477x over previous
#include <cuda_runtime.h>
#include <cuda_fp16.h>
#include <mma.h>
#include <cstdint>

using namespace nvcuda;

// Problem constants (fixed by the reference)
#define NMAX 100000
#define EMAX 1250000
#define HDIM 64
#define NCLS 10
#define SCAN_CHUNK 1024
#define MAXBLK 128   // ceil(NMAX/SCAN_CHUNK) = 98 <= 128

// Scratch: __device__ globals (allocation APIs are forbidden).
__device__ __align__(16)  float  g_t2[NMAX * HDIM];   // fp32 messages (self term)
__device__ __align__(128) __half g_t2h[NMAX * HDIM];  // fp16 messages (neighbor reads)
__device__ __align__(16)  float  g_h [NMAX * HDIM];   // layer output
__device__ float g_dinv[NMAX];
__device__ int   g_cnt[NMAX];
__device__ int   g_rowptr[NMAX + 1];
__device__ int   g_eidx[EMAX];
__device__ int   g_bsum[MAXBLK];
__device__ int   g_boff[MAXBLK];

// ---------------------------------------------------------------------------
__global__ void k_zerocnt(int n) {
    int i = blockIdx.x * blockDim.x + threadIdx.x;
    if (i < n) g_cnt[i] = 0;
}

__global__ void k_hist(const int* __restrict__ ei, int e, int n) {
    int idx = blockIdx.x * blockDim.x + threadIdx.x;
    if (idx < e) {
        int d = ei[e + idx];
        if (d >= 0 && d < n) atomicAdd(&g_cnt[d], 1);
    }
}

__global__ void k_dinvk(int n) {
    int i = blockIdx.x * blockDim.x + threadIdx.x;
    if (i < n) g_dinv[i] = rsqrtf((float)(g_cnt[i] + 1));
}

// ---------------------------------------------------------------------------
// Parallel 3-phase exclusive scan of g_cnt -> g_rowptr.
__global__ void k_blocksum(int n) {
    const int t = threadIdx.x;
    const int base = blockIdx.x * SCAN_CHUNK + t * 4;
    int s = 0;
#pragma unroll
    for (int j = 0; j < 4; j++) {
        int i = base + j;
        if (i < n) s += g_cnt[i];
    }
#pragma unroll
    for (int off = 16; off > 0; off >>= 1)
        s += __shfl_down_sync(0xffffffffu, s, off);
    __shared__ int wsum[8];
    if ((t & 31) == 0) wsum[t >> 5] = s;
    __syncthreads();
    if (t == 0) {
        int tot = 0;
#pragma unroll
        for (int w = 0; w < 8; w++) tot += wsum[w];
        g_bsum[blockIdx.x] = tot;
    }
}

__global__ void k_scanb(int nb, int n) {
    const int t = threadIdx.x;       // 128 threads
    int v = (t < nb) ? g_bsum[t] : 0;
    int own = v;
    int lane = t & 31, w = t >> 5;
#pragma unroll
    for (int off = 1; off < 32; off <<= 1) {
        int u = __shfl_up_sync(0xffffffffu, v, off);
        if (lane >= off) v += u;
    }
    __shared__ int wtot[4], woff[4];
    if (lane == 31) wtot[w] = v;
    __syncthreads();
    if (t == 0) {
        int run = 0;
#pragma unroll
        for (int i = 0; i < 4; i++) { woff[i] = run; run += wtot[i]; }
        g_rowptr[n] = run;           // total edge count
    }
    __syncthreads();
    int incl = v + woff[w];
    if (t < nb) g_boff[t] = incl - own;   // exclusive
}

__global__ void k_rowptr(int n) {
    const int t = threadIdx.x;       // 256 threads
    const int base = blockIdx.x * SCAN_CHUNK + t * 4;
    int c[4];
    int s = 0;
#pragma unroll
    for (int j = 0; j < 4; j++) {
        int i = base + j;
        c[j] = (i < n) ? g_cnt[i] : 0;
        s += c[j];
    }
    int v = s, own = s;
    int lane = t & 31, w = t >> 5;
#pragma unroll
    for (int off = 1; off < 32; off <<= 1) {
        int u = __shfl_up_sync(0xffffffffu, v, off);
        if (lane >= off) v += u;
    }
    __shared__ int wtot[8], woff[8];
    if (lane == 31) wtot[w] = v;
    __syncthreads();
    if (t == 0) {
        int run = 0;
#pragma unroll
        for (int i = 0; i < 8; i++) { woff[i] = run; run += wtot[i]; }
    }
    __syncthreads();
    int excl = (v - own) + woff[w] + g_boff[blockIdx.x];
#pragma unroll
    for (int j = 0; j < 4; j++) {
        int i = base + j;
        if (i < n) {
            g_rowptr[i] = excl;
            excl += c[j];
            g_cnt[i] = 0;            // reset fill cursor
        }
    }
}

__global__ void k_fill(const int* __restrict__ ei, int e, int n) {
    int idx = blockIdx.x * blockDim.x + threadIdx.x;
    if (idx < e) {
        int s = ei[idx];
        int d = ei[e + idx];
        if (s >= 0 && s < n && d >= 0 && d < n) {
            int pos = g_rowptr[d] + atomicAdd(&g_cnt[d], 1);
            if (pos < EMAX) g_eidx[pos] = s;
        }
    }
}

// ---------------------------------------------------------------------------
// Tensor-core GEMM: t2 = dinv ⊙ ((relu?)hin @ W), fp32 + fp16 outputs.
// BM=128 rows/block, 256 threads = 8 warps. Warp w computes rows
// [16w, 16w+16) x all 64 cols: 4 fp32 accum frags, K-loop of 4 mma steps.
// Inputs converted to fp16 in smem (HMMA, fp32 accumulate).
// Epilogue stages fp32 results in smem (aliased over the input tiles after
// __syncthreads), scales by dinv, writes fp32 t2 + fp16 t2h.
#define HLD 72                      // fp16 smem row stride (pad vs conflicts)
__global__ void __launch_bounds__(256) k_matmul(
        const float* __restrict__ xin, int use_x,
        const float* __restrict__ W, int n, int relu) {
    __shared__ __align__(32) char smem[32768];   // 32 KB, aliased
    __half (*Hsh)[HLD] = (__half(*)[HLD])smem;                 // 128x72 fp16 = 18KB
    __half (*Wsh)[HLD] = (__half(*)[HLD])(smem + 128 * HLD * 2); // 64x72 fp16 = 9KB
    float* Osh = (float*)smem;                                  // 8 x (16x64) fp32 = 32KB

    const float* hin = use_x ? xin : g_h;
    const int tid = threadIdx.x;
    const int r0  = blockIdx.x * 128;
    const int lane = tid & 31;
    const int w    = tid >> 5;      // warp 0..7

    // Load W (64x64 fp32 -> fp16): 1024 float4 slots / 256 threads = 4 iters
#pragma unroll
    for (int i = 0; i < 4; i++) {
        int idx = tid + 256 * i;     // 0..1023
        int row = idx >> 4;
        int c4  = idx & 15;
        float4 v = *(const float4*)(W + row * 64 + c4 * 4);
        __half* p = &Wsh[row][c4 * 4];
        p[0] = __float2half_rn(v.x); p[1] = __float2half_rn(v.y);
        p[2] = __float2half_rn(v.z); p[3] = __float2half_rn(v.w);
    }

    // Load H tile (128x64 fp32 -> fp16), optional relu
#pragma unroll
    for (int i = 0; i < 8; i++) {
        int idx = tid + 256 * i;     // 0..2047
        int row = idx >> 4;
        int c4  = idx & 15;
        int gr  = r0 + row;
        float4 v = make_float4(0.f, 0.f, 0.f, 0.f);
        if (gr < n) v = *(const float4*)(hin + (size_t)gr * 64 + c4 * 4);
        if (relu) {
            v.x = fmaxf(v.x, 0.f); v.y = fmaxf(v.y, 0.f);
            v.z = fmaxf(v.z, 0.f); v.w = fmaxf(v.w, 0.f);
        }
        __half* p = &Hsh[row][c4 * 4];
        p[0] = __float2half_rn(v.x); p[1] = __float2half_rn(v.y);
        p[2] = __float2half_rn(v.z); p[3] = __float2half_rn(v.w);
    }
    __syncthreads();

    // MMA: warp w -> rows [16w, 16w+16)
    wmma::fragment<wmma::accumulator, 16, 16, 16, float> c[4];
#pragma unroll
    for (int j = 0; j < 4; j++) wmma::fill_fragment(c[j], 0.0f);

#pragma unroll
    for (int k = 0; k < 4; k++) {
        wmma::fragment<wmma::matrix_a, 16, 16, 16, __half, wmma::row_major> a;
        wmma::load_matrix_sync(a, &Hsh[w * 16][k * 16], HLD);
#pragma unroll
        for (int j = 0; j < 4; j++) {
            wmma::fragment<wmma::matrix_b, 16, 16, 16, __half, wmma::row_major> b;
            wmma::load_matrix_sync(b, &Wsh[k * 16][j * 16], HLD);
            wmma::mma_sync(c[j], a, b, c[j]);
        }
    }

    // Frags live in registers; now safe to re-use smem as fp32 staging.
    __syncthreads();
    float* stage = Osh + w * (16 * 64);          // this warp's 16x64 strip
#pragma unroll
    for (int j = 0; j < 4; j++)
        wmma::store_matrix_sync(stage + j * 16, c[j], 64, wmma::mem_row_major);
    __syncwarp();

    // Epilogue: scale by dinv, write fp32 t2 + fp16 t2h (warp-local strip)
#pragma unroll
    for (int it = 0; it < 8; it++) {
        int slot = lane + it * 32;               // 0..255 float4 slots
        int row  = slot >> 4;                    // 0..15
        int c4   = slot & 15;
        int grow = r0 + w * 16 + row;
        if (grow < n) {
            float di = g_dinv[grow];
            float4 v = *(float4*)(stage + row * 64 + c4 * 4);
            v.x *= di; v.y *= di; v.z *= di; v.w *= di;
            size_t base = (size_t)grow * 64 + c4 * 4;
            *(float4*)(g_t2 + base) = v;
            __half2 p0 = __floats2half2_rn(v.x, v.y);
            __half2 p1 = __floats2half2_rn(v.z, v.w);
            uint2 hp;
            hp.x = *(const unsigned int*)&p0;
            hp.y = *(const unsigned int*)&p1;
            *(uint2*)(g_t2h + base) = hp;
        }
    }
}

// ---------------------------------------------------------------------------
// Gather: h[i] = dinv[i]*(t2[i] + sum_{e: dst=i} fp16(t2[src_e])) + b
// 16 threads per node; neighbor rows read as fp16 (8 B/thread), fp32 accum.
__global__ void k_gather(const float* __restrict__ b, int n) {
    int gid = blockIdx.x * blockDim.x + threadIdx.x;
    int node = gid >> 4;
    if (node >= n) return;
    int q = (gid & 15) << 2;

    float4 acc = *(const float4*)(g_t2 + ((size_t)node << 6) + q);
    float4 acc2 = make_float4(0.f, 0.f, 0.f, 0.f);

    int k   = g_rowptr[node];
    int end = g_rowptr[node + 1];

    const __half* t2h = g_t2h;

    for (; k + 4 <= end; k += 4) {
        int s0 = __ldg(&g_eidx[k]);
        int s1 = __ldg(&g_eidx[k + 1]);
        int s2 = __ldg(&g_eidx[k + 2]);
        int s3 = __ldg(&g_eidx[k + 3]);
        uint2 r0 = *(const uint2*)(t2h + ((size_t)s0 << 6) + q);
        uint2 r1 = *(const uint2*)(t2h + ((size_t)s1 << 6) + q);
        uint2 r2 = *(const uint2*)(t2h + ((size_t)s2 << 6) + q);
        uint2 r3 = *(const uint2*)(t2h + ((size_t)s3 << 6) + q);
        float2 a0 = __half22float2(*(const __half2*)&r0.x);
        float2 b0 = __half22float2(*(const __half2*)&r0.y);
        float2 a1 = __half22float2(*(const __half2*)&r1.x);
        float2 b1 = __half22float2(*(const __half2*)&r1.y);
        float2 a2 = __half22float2(*(const __half2*)&r2.x);
        float2 b2 = __half22float2(*(const __half2*)&r2.y);
        float2 a3 = __half22float2(*(const __half2*)&r3.x);
        float2 b3 = __half22float2(*(const __half2*)&r3.y);
        acc.x  += a0.x + a1.x;  acc.y  += a0.y + a1.y;
        acc.z  += b0.x + b1.x;  acc.w  += b0.y + b1.y;
        acc2.x += a2.x + a3.x;  acc2.y += a2.y + a3.y;
        acc2.z += b2.x + b3.x;  acc2.w += b2.y + b3.y;
    }
    for (; k < end; k++) {
        int s0 = __ldg(&g_eidx[k]);
        uint2 r0 = *(const uint2*)(t2h + ((size_t)s0 << 6) + q);
        float2 a0 = __half22float2(*(const __half2*)&r0.x);
        float2 b0 = __half22float2(*(const __half2*)&r0.y);
        acc.x += a0.x; acc.y += a0.y; acc.z += b0.x; acc.w += b0.y;
    }
    acc.x += acc2.x; acc.y += acc2.y; acc.z += acc2.z; acc.w += acc2.w;

    float di = g_dinv[node];
    float4 bb = *(const float4*)(b + q);
    float4 o;
    o.x = fmaf(di, acc.x, bb.x);
    o.y = fmaf(di, acc.y, bb.y);
    o.z = fmaf(di, acc.z, bb.z);
    o.w = fmaf(di, acc.w, bb.w);
    *(float4*)(g_h + ((size_t)node << 6) + q) = o;
}

// ---------------------------------------------------------------------------
// Fused mean-pool (batch sorted -> binary search segments) + linear head.
__global__ void k_pool(const int* __restrict__ batch,
                       const float* __restrict__ Wl, const float* __restrict__ bl,
                       float* __restrict__ out, int n) {
    const float* h = g_h;
    const int g = blockIdx.x;
    const int t = threadIdx.x;
    const int c = t & 63;
    const int j = t >> 6;

    auto lb = [&](int key) {
        int lo = 0, hi = n;
        while (lo < hi) {
            int mid = (lo + hi) >> 1;
            if (batch[mid] < key) lo = mid + 1; else hi = mid;
        }
        return lo;
    };
    int lo = lb(g);
    int hi = lb(g + 1);
    int cnt = hi - lo;

    float s = 0.f;
    for (int i = lo + j; i < hi; i += 4)
        s += h[(size_t)i * 64 + c];

    __shared__ float red[256];
    red[t] = s;
    __syncthreads();

    __shared__ float pooled[64];
    if (t < 64) {
        float tot = red[t] + red[t + 64] + red[t + 128] + red[t + 192];
        pooled[t] = tot / (float)max(cnt, 1);
    }
    __syncthreads();

    if (t < NCLS) {
        float acc = bl[t];
#pragma unroll
        for (int k = 0; k < 64; k++)
            acc = fmaf(pooled[k], Wl[k * NCLS + t], acc);
        out[g * NCLS + t] = acc;
    }
}

// ---------------------------------------------------------------------------
extern "C" void kernel_launch(void* const* d_in, const int* in_sizes, int n_in,
                              void* d_out, int out_size) {
    // Resolve inputs BY ELEMENT COUNT (robust to metadata ordering).
    const float* x     = nullptr;
    const int*   ei    = nullptr;
    const int*   batch = nullptr;
    const float* W[3] = {nullptr, nullptr, nullptr};
    const float* B[3] = {nullptr, nullptr, nullptr};
    const float* Wl = nullptr;
    const float* bl = nullptr;
    int nW = 0, nB = 0;
    long long eiCount = 0, batchCount = 0;

    for (int i = 0; i < n_in; i++) {
        long long sz = in_sizes[i];
        if (sz == 10)            bl = (const float*)d_in[i];
        else if (sz == 640)      Wl = (const float*)d_in[i];
        else if (sz == HDIM)     { if (nB < 3) B[nB++] = (const float*)d_in[i]; }
        else if (sz == HDIM*HDIM){ if (nW < 3) W[nW++] = (const float*)d_in[i]; }
        else {
            if (sz >= 6000000)       x = (const float*)d_in[i];
            else if (sz >= 2000000)  { ei = (const int*)d_in[i]; eiCount = sz; }
            else                     { batch = (const int*)d_in[i]; batchCount = sz; }
        }
    }

    float* out = (float*)d_out;
    const int n = (int)batchCount;            // N nodes
    const int e = (int)(eiCount / 2);         // E edges
    const int g = out_size / NCLS;            // G graphs

    const int tb = 256;
    const int nb = (n + SCAN_CHUNK - 1) / SCAN_CHUNK;   // scan blocks (98)
    const int mmGrid = (n + 127) / 128;
    const int gaGrid = (n * 16 + tb - 1) / tb;

    // Launch order keeps matmul layer-1 at slot #4 (the ncu-captured launch).
    k_zerocnt <<<(n + tb - 1) / tb, tb>>>(n);            // 1
    k_hist    <<<(e + tb - 1) / tb, tb>>>(ei, e, n);     // 2
    k_dinvk   <<<(n + tb - 1) / tb, tb>>>(n);            // 3
    k_matmul  <<<mmGrid, 256>>>(x, 1, W[0], n, 0);       // 4  <- profiled
    k_blocksum<<<nb, tb>>>(n);                           // 5
    k_scanb   <<<1, 128>>>(nb, n);                       // 6
    k_rowptr  <<<nb, tb>>>(n);                           // 7
    k_fill    <<<(e + tb - 1) / tb, tb>>>(ei, e, n);     // 8
    k_gather  <<<gaGrid, tb>>>(B[0], n);                 // 9
    k_matmul  <<<mmGrid, 256>>>(nullptr, 0, W[1], n, 1); // 10
    k_gather  <<<gaGrid, tb>>>(B[1], n);                 // 11
    k_matmul  <<<mmGrid, 256>>>(nullptr, 0, W[2], n, 1); // 12
    k_gather  <<<gaGrid, tb>>>(B[2], n);                 // 13
    k_pool    <<<g, tb>>>(batch, Wl, bl, out, n);        // 14
}

// round 14
// speedup vs baseline: 1.7353x; 1.1212x over previous
#include <cuda_runtime.h>
#include <cuda_fp16.h>
#include <mma.h>
#include <cstdint>

using namespace nvcuda;

// Problem constants (fixed by the reference)
#define NMAX 100000
#define EMAX 1250000
#define HDIM 64
#define NCLS 10
#define SCAN_CHUNK 1024
#define MAXBLK 128   // ceil(NMAX/SCAN_CHUNK) = 98 <= 128

// Scratch: __device__ globals (allocation APIs are forbidden).
// fp16 storage end-to-end; fp32 accumulation inside kernels.
__device__ __align__(128) __half g_t2h[NMAX * HDIM];  // messages (dinv-prescaled)
__device__ __align__(128) __half g_hh [NMAX * HDIM];  // layer output
__device__ float g_dinv[NMAX];
__device__ int   g_cnt[NMAX];
__device__ int   g_rowptr[NMAX + 1];
__device__ int   g_eidx[EMAX];
__device__ int   g_bsum[MAXBLK];
__device__ int   g_boff[MAXBLK];

// ---------------------------------------------------------------------------
__global__ void k_zerocnt(int n) {
    int i = blockIdx.x * blockDim.x + threadIdx.x;
    if (i < n) g_cnt[i] = 0;
}

__global__ void k_hist(const int* __restrict__ ei, int e, int n) {
    int idx = blockIdx.x * blockDim.x + threadIdx.x;
    if (idx < e) {
        int d = ei[e + idx];
        if (d >= 0 && d < n) atomicAdd(&g_cnt[d], 1);
    }
}

// ---------------------------------------------------------------------------
// Scan phase 1 (per-block sums) FUSED with dinv computation.
__global__ void k_blocksum(int n) {
    const int t = threadIdx.x;
    const int base = blockIdx.x * SCAN_CHUNK + t * 4;
    int s = 0;
#pragma unroll
    for (int j = 0; j < 4; j++) {
        int i = base + j;
        if (i < n) {
            int c = g_cnt[i];
            s += c;
            g_dinv[i] = rsqrtf((float)(c + 1));   // deg incl. self loop
        }
    }
#pragma unroll
    for (int off = 16; off > 0; off >>= 1)
        s += __shfl_down_sync(0xffffffffu, s, off);
    __shared__ int wsum[8];
    if ((t & 31) == 0) wsum[t >> 5] = s;
    __syncthreads();
    if (t == 0) {
        int tot = 0;
#pragma unroll
        for (int w = 0; w < 8; w++) tot += wsum[w];
        g_bsum[blockIdx.x] = tot;
    }
}

__global__ void k_scanb(int nb, int n) {
    const int t = threadIdx.x;       // 128 threads
    int v = (t < nb) ? g_bsum[t] : 0;
    int own = v;
    int lane = t & 31, w = t >> 5;
#pragma unroll
    for (int off = 1; off < 32; off <<= 1) {
        int u = __shfl_up_sync(0xffffffffu, v, off);
        if (lane >= off) v += u;
    }
    __shared__ int wtot[4], woff[4];
    if (lane == 31) wtot[w] = v;
    __syncthreads();
    if (t == 0) {
        int run = 0;
#pragma unroll
        for (int i = 0; i < 4; i++) { woff[i] = run; run += wtot[i]; }
        g_rowptr[n] = run;           // total edge count
    }
    __syncthreads();
    int incl = v + woff[w];
    if (t < nb) g_boff[t] = incl - own;   // exclusive
}

__global__ void k_rowptr(int n) {
    const int t = threadIdx.x;       // 256 threads
    const int base = blockIdx.x * SCAN_CHUNK + t * 4;
    int c[4];
    int s = 0;
#pragma unroll
    for (int j = 0; j < 4; j++) {
        int i = base + j;
        c[j] = (i < n) ? g_cnt[i] : 0;
        s += c[j];
    }
    int v = s, own = s;
    int lane = t & 31, w = t >> 5;
#pragma unroll
    for (int off = 1; off < 32; off <<= 1) {
        int u = __shfl_up_sync(0xffffffffu, v, off);
        if (lane >= off) v += u;
    }
    __shared__ int wtot[8], woff[8];
    if (lane == 31) wtot[w] = v;
    __syncthreads();
    if (t == 0) {
        int run = 0;
#pragma unroll
        for (int i = 0; i < 8; i++) { woff[i] = run; run += wtot[i]; }
    }
    __syncthreads();
    int excl = (v - own) + woff[w] + g_boff[blockIdx.x];
#pragma unroll
    for (int j = 0; j < 4; j++) {
        int i = base + j;
        if (i < n) {
            g_rowptr[i] = excl;
            excl += c[j];
            g_cnt[i] = 0;            // reset fill cursor
        }
    }
}

__global__ void k_fill(const int* __restrict__ ei, int e, int n) {
    int idx = blockIdx.x * blockDim.x + threadIdx.x;
    if (idx < e) {
        int s = ei[idx];
        int d = ei[e + idx];
        if (s >= 0 && s < n && d >= 0 && d < n) {
            int pos = g_rowptr[d] + atomicAdd(&g_cnt[d], 1);
            if (pos < EMAX) g_eidx[pos] = s;
        }
    }
}

// ---------------------------------------------------------------------------
// Tensor-core GEMM: t2h = fp16( dinv ⊙ ((relu?)hin @ W) ).
// BM=128 rows/block, 256 threads = 8 warps; warp w -> rows [16w,16w+16).
// Layer 1 reads fp32 x; layers 2/3 read fp16 g_hh (relu fused, __hmax2).
#define HLD 72                      // fp16 smem row stride (pad vs conflicts)
__global__ void __launch_bounds__(256) k_matmul(
        const float* __restrict__ xin, int use_x,
        const float* __restrict__ W, int n, int relu) {
    __shared__ __align__(32) char smem[32768];   // 32 KB, aliased
    __half (*Hsh)[HLD] = (__half(*)[HLD])smem;                   // 128x72 fp16
    __half (*Wsh)[HLD] = (__half(*)[HLD])(smem + 128 * HLD * 2); // 64x72 fp16
    float* Osh = (float*)smem;                                   // 8x(16x64) fp32

    const int tid = threadIdx.x;
    const int r0  = blockIdx.x * 128;
    const int lane = tid & 31;
    const int w    = tid >> 5;      // warp 0..7

    // Load W (64x64 fp32 -> fp16): 1024 float4 slots / 256 threads = 4 iters
#pragma unroll
    for (int i = 0; i < 4; i++) {
        int idx = tid + 256 * i;     // 0..1023
        int row = idx >> 4;
        int c4  = idx & 15;
        float4 v = *(const float4*)(W + row * 64 + c4 * 4);
        __half* p = &Wsh[row][c4 * 4];
        p[0] = __float2half_rn(v.x); p[1] = __float2half_rn(v.y);
        p[2] = __float2half_rn(v.z); p[3] = __float2half_rn(v.w);
    }

    // Load H tile (128 rows x 64 cols)
    if (use_x) {
        // fp32 input, convert (no relu on raw features)
#pragma unroll
        for (int i = 0; i < 8; i++) {
            int idx = tid + 256 * i;     // 0..2047 float4 slots
            int row = idx >> 4;
            int c4  = idx & 15;
            int gr  = r0 + row;
            float4 v = make_float4(0.f, 0.f, 0.f, 0.f);
            if (gr < n) v = *(const float4*)(xin + (size_t)gr * 64 + c4 * 4);
            __half* p = &Hsh[row][c4 * 4];
            p[0] = __float2half_rn(v.x); p[1] = __float2half_rn(v.y);
            p[2] = __float2half_rn(v.z); p[3] = __float2half_rn(v.w);
        }
    } else {
        // fp16 input straight from g_hh, fused relu
        const __half2 z2 = __float2half2_rn(0.f);
#pragma unroll
        for (int i = 0; i < 4; i++) {
            int idx = tid + 256 * i;     // 0..1023 uint4 slots (8 halves each)
            int row = idx >> 3;
            int c8  = idx & 7;
            int gr  = r0 + row;
            uint4 v = make_uint4(0u, 0u, 0u, 0u);
            if (gr < n) v = *(const uint4*)(g_hh + (size_t)gr * 64 + c8 * 8);
            if (relu) {
                __half2* h2 = (__half2*)&v;
                h2[0] = __hmax2(h2[0], z2);
                h2[1] = __hmax2(h2[1], z2);
                h2[2] = __hmax2(h2[2], z2);
                h2[3] = __hmax2(h2[3], z2);
            }
            *(uint4*)&Hsh[row][c8 * 8] = v;
        }
    }
    __syncthreads();

    // MMA: warp w -> rows [16w, 16w+16)
    wmma::fragment<wmma::accumulator, 16, 16, 16, float> c[4];
#pragma unroll
    for (int j = 0; j < 4; j++) wmma::fill_fragment(c[j], 0.0f);

#pragma unroll
    for (int k = 0; k < 4; k++) {
        wmma::fragment<wmma::matrix_a, 16, 16, 16, __half, wmma::row_major> a;
        wmma::load_matrix_sync(a, &Hsh[w * 16][k * 16], HLD);
#pragma unroll
        for (int j = 0; j < 4; j++) {
            wmma::fragment<wmma::matrix_b, 16, 16, 16, __half, wmma::row_major> b;
            wmma::load_matrix_sync(b, &Wsh[k * 16][j * 16], HLD);
            wmma::mma_sync(c[j], a, b, c[j]);
        }
    }

    // Frags in registers; reuse smem as fp32 staging.
    __syncthreads();
    float* stage = Osh + w * (16 * 64);          // this warp's 16x64 strip
#pragma unroll
    for (int j = 0; j < 4; j++)
        wmma::store_matrix_sync(stage + j * 16, c[j], 64, wmma::mem_row_major);
    __syncwarp();

    // Epilogue: scale by dinv, write fp16 t2h only
#pragma unroll
    for (int it = 0; it < 8; it++) {
        int slot = lane + it * 32;               // 0..255 float4 slots
        int row  = slot >> 4;                    // 0..15
        int c4   = slot & 15;
        int grow = r0 + w * 16 + row;
        if (grow < n) {
            float di = g_dinv[grow];
            float4 v = *(float4*)(stage + row * 64 + c4 * 4);
            __half2 p0 = __floats2half2_rn(v.x * di, v.y * di);
            __half2 p1 = __floats2half2_rn(v.z * di, v.w * di);
            uint2 hp;
            hp.x = *(const unsigned int*)&p0;
            hp.y = *(const unsigned int*)&p1;
            *(uint2*)(g_t2h + (size_t)grow * 64 + c4 * 4) = hp;
        }
    }
}

// ---------------------------------------------------------------------------
// Gather: h[i] = fp16( dinv[i]*(t2h[i] + sum_{e: dst=i} t2h[src_e]) + b )
// 16 threads per node, 4 halves (8 B) per thread, fp32 accumulation.
__global__ void k_gather(const float* __restrict__ b, int n) {
    int gid = blockIdx.x * blockDim.x + threadIdx.x;
    int node = gid >> 4;
    if (node >= n) return;
    int q = (gid & 15) << 2;                 // half-column base

    const __half* t2h = g_t2h;

    uint2 rs = *(const uint2*)(t2h + ((size_t)node << 6) + q);
    float2 sa = __half22float2(*(const __half2*)&rs.x);
    float2 sb = __half22float2(*(const __half2*)&rs.y);
    float4 acc = make_float4(sa.x, sa.y, sb.x, sb.y);
    float4 acc2 = make_float4(0.f, 0.f, 0.f, 0.f);

    int k   = g_rowptr[node];
    int end = g_rowptr[node + 1];

    for (; k + 4 <= end; k += 4) {
        int s0 = __ldg(&g_eidx[k]);
        int s1 = __ldg(&g_eidx[k + 1]);
        int s2 = __ldg(&g_eidx[k + 2]);
        int s3 = __ldg(&g_eidx[k + 3]);
        uint2 r0 = *(const uint2*)(t2h + ((size_t)s0 << 6) + q);
        uint2 r1 = *(const uint2*)(t2h + ((size_t)s1 << 6) + q);
        uint2 r2 = *(const uint2*)(t2h + ((size_t)s2 << 6) + q);
        uint2 r3 = *(const uint2*)(t2h + ((size_t)s3 << 6) + q);
        float2 a0 = __half22float2(*(const __half2*)&r0.x);
        float2 b0 = __half22float2(*(const __half2*)&r0.y);
        float2 a1 = __half22float2(*(const __half2*)&r1.x);
        float2 b1 = __half22float2(*(const __half2*)&r1.y);
        float2 a2 = __half22float2(*(const __half2*)&r2.x);
        float2 b2 = __half22float2(*(const __half2*)&r2.y);
        float2 a3 = __half22float2(*(const __half2*)&r3.x);
        float2 b3 = __half22float2(*(const __half2*)&r3.y);
        acc.x  += a0.x + a1.x;  acc.y  += a0.y + a1.y;
        acc.z  += b0.x + b1.x;  acc.w  += b0.y + b1.y;
        acc2.x += a2.x + a3.x;  acc2.y += a2.y + a3.y;
        acc2.z += b2.x + b3.x;  acc2.w += b2.y + b3.y;
    }
    for (; k < end; k++) {
        int s0 = __ldg(&g_eidx[k]);
        uint2 r0 = *(const uint2*)(t2h + ((size_t)s0 << 6) + q);
        float2 a0 = __half22float2(*(const __half2*)&r0.x);
        float2 b0 = __half22float2(*(const __half2*)&r0.y);
        acc.x += a0.x; acc.y += a0.y; acc.z += b0.x; acc.w += b0.y;
    }
    acc.x += acc2.x; acc.y += acc2.y; acc.z += acc2.z; acc.w += acc2.w;

    float di = g_dinv[node];
    float4 bb = *(const float4*)(b + q);
    __half2 h0 = __floats2half2_rn(fmaf(di, acc.x, bb.x), fmaf(di, acc.y, bb.y));
    __half2 h1 = __floats2half2_rn(fmaf(di, acc.z, bb.z), fmaf(di, acc.w, bb.w));
    uint2 hp;
    hp.x = *(const unsigned int*)&h0;
    hp.y = *(const unsigned int*)&h1;
    *(uint2*)(g_hh + ((size_t)node << 6) + q) = hp;
}

// ---------------------------------------------------------------------------
// Fused mean-pool (batch sorted -> binary search segments) + linear head.
__global__ void k_pool(const int* __restrict__ batch,
                       const float* __restrict__ Wl, const float* __restrict__ bl,
                       float* __restrict__ out, int n) {
    const __half* h = g_hh;
    const int g = blockIdx.x;
    const int t = threadIdx.x;
    const int c = t & 63;
    const int j = t >> 6;

    auto lb = [&](int key) {
        int lo = 0, hi = n;
        while (lo < hi) {
            int mid = (lo + hi) >> 1;
            if (batch[mid] < key) lo = mid + 1; else hi = mid;
        }
        return lo;
    };
    int lo = lb(g);
    int hi = lb(g + 1);
    int cnt = hi - lo;

    float s = 0.f;
    for (int i = lo + j; i < hi; i += 4)
        s += __half2float(h[(size_t)i * 64 + c]);

    __shared__ float red[256];
    red[t] = s;
    __syncthreads();

    __shared__ float pooled[64];
    if (t < 64) {
        float tot = red[t] + red[t + 64] + red[t + 128] + red[t + 192];
        pooled[t] = tot / (float)max(cnt, 1);
    }
    __syncthreads();

    if (t < NCLS) {
        float acc = bl[t];
#pragma unroll
        for (int k = 0; k < 64; k++)
            acc = fmaf(pooled[k], Wl[k * NCLS + t], acc);
        out[g * NCLS + t] = acc;
    }
}

// ---------------------------------------------------------------------------
extern "C" void kernel_launch(void* const* d_in, const int* in_sizes, int n_in,
                              void* d_out, int out_size) {
    // Resolve inputs BY ELEMENT COUNT (robust to metadata ordering).
    const float* x     = nullptr;
    const int*   ei    = nullptr;
    const int*   batch = nullptr;
    const float* W[3] = {nullptr, nullptr, nullptr};
    const float* B[3] = {nullptr, nullptr, nullptr};
    const float* Wl = nullptr;
    const float* bl = nullptr;
    int nW = 0, nB = 0;
    long long eiCount = 0, batchCount = 0;

    for (int i = 0; i < n_in; i++) {
        long long sz = in_sizes[i];
        if (sz == 10)            bl = (const float*)d_in[i];
        else if (sz == 640)      Wl = (const float*)d_in[i];
        else if (sz == HDIM)     { if (nB < 3) B[nB++] = (const float*)d_in[i]; }
        else if (sz == HDIM*HDIM){ if (nW < 3) W[nW++] = (const float*)d_in[i]; }
        else {
            if (sz >= 6000000)       x = (const float*)d_in[i];
            else if (sz >= 2000000)  { ei = (const int*)d_in[i]; eiCount = sz; }
            else                     { batch = (const int*)d_in[i]; batchCount = sz; }
        }
    }

    float* out = (float*)d_out;
    const int n = (int)batchCount;            // N nodes
    const int e = (int)(eiCount / 2);         // E edges
    const int g = out_size / NCLS;            // G graphs

    const int tb = 256;
    const int nb = (n + SCAN_CHUNK - 1) / SCAN_CHUNK;   // scan blocks (98)
    const int mmGrid = (n + 127) / 128;
    const int gaGrid = (n * 16 + tb - 1) / tb;

    // Launch order keeps matmul layer-1 at slot #4 (the ncu-captured launch).
    k_zerocnt <<<(n + tb - 1) / tb, tb>>>(n);            // 1
    k_hist    <<<(e + tb - 1) / tb, tb>>>(ei, e, n);     // 2
    k_blocksum<<<nb, tb>>>(n);                           // 3 (fused dinv)
    k_matmul  <<<mmGrid, 256>>>(x, 1, W[0], n, 0);       // 4  <- profiled
    k_scanb   <<<1, 128>>>(nb, n);                       // 5
    k_rowptr  <<<nb, tb>>>(n);                           // 6
    k_fill    <<<(e + tb - 1) / tb, tb>>>(ei, e, n);     // 7
    k_gather  <<<gaGrid, tb>>>(B[0], n);                 // 8
    k_matmul  <<<mmGrid, 256>>>(nullptr, 0, W[1], n, 1); // 9
    k_gather  <<<gaGrid, tb>>>(B[1], n);                 // 10
    k_matmul  <<<mmGrid, 256>>>(nullptr, 0, W[2], n, 1); // 11
    k_gather  <<<gaGrid, tb>>>(B[2], n);                 // 12
    k_pool    <<<g, tb>>>(batch, Wl, bl, out, n);        // 13
}